// round 3
// baseline (speedup 1.0000x reference)
#include <cuda_runtime.h>

// out[b,c,h,w] = max over 4 directional 3x3 Laplacians (zero-padded):
//   lap0 = x[h,w-1] + x[h,w+1] - 2x      (horizontal)
//   lap1 = x[h-1,w] + x[h+1,w] - 2x      (vertical)
//   lap2 = x[h-1,w+1] + x[h+1,w-1] - 2x  (anti-diagonal)
//   lap3 = x[h-1,w-1] + x[h+1,w+1] - 2x  (diagonal)

#define W   512
#define H   512
#define RPT 8    // rows per thread
#define TW  8    // pixels per thread (width)

// Load a 10-wide window [w0-1 .. w0+8] of row h into a[0..9], zero-padded.
__device__ __forceinline__ void load_row10(const float* __restrict__ img,
                                           int h, int w0, float a[10]) {
    if ((unsigned)h >= (unsigned)H) {
        #pragma unroll
        for (int i = 0; i < 10; i++) a[i] = 0.f;
        return;
    }
    const float* row = img + h * W;
    float4 v0 = __ldg((const float4*)(row + w0));
    float4 v1 = __ldg((const float4*)(row + w0 + 4));
    a[1] = v0.x; a[2] = v0.y; a[3] = v0.z; a[4] = v0.w;
    a[5] = v1.x; a[6] = v1.y; a[7] = v1.z; a[8] = v1.w;
    a[0] = (w0 > 0)        ? __ldg(row + w0 - 1) : 0.f;  // L1 hit (same/adjacent line)
    a[9] = (w0 + TW < W)   ? __ldg(row + w0 + TW) : 0.f;
}

__global__ __launch_bounds__(128, 8)
void maxlap_kernel(const float* __restrict__ x, float* __restrict__ out) {
    const int tx = threadIdx.x & 63;   // 64 threads cover 512 width (8 px each)
    const int ty = threadIdx.x >> 6;   // 2 row-strips per block
    const int w0 = tx * TW;
    const int h0 = (blockIdx.x * 2 + ty) * RPT;
    const int img = blockIdx.y;

    const float* in  = x   + (size_t)img * H * W;
    float*       dst = out + (size_t)img * H * W;

    // 4 rotating register windows: at iteration rr,
    //   top = win[rr&3], mid = win[(rr+1)&3], bot = win[(rr+2)&3],
    //   prefetch row h0+rr+2 into win[(rr+3)&3].
    float win[4][10];
    load_row10(in, h0 - 1, w0, win[0]);
    load_row10(in, h0,     w0, win[1]);
    load_row10(in, h0 + 1, w0, win[2]);

    #pragma unroll
    for (int rr = 0; rr < RPT; rr++) {
        if (rr < RPT - 1)
            load_row10(in, h0 + rr + 2, w0, win[(rr + 3) & 3]);  // prefetch, 1 iter ahead

        float o[TW];
        #pragma unroll
        for (int i = 0; i < TW; i++) {
            const float c  = win[(rr + 1) & 3][i + 1];
            const float c2 = c + c;
            const float lap0 = (win[(rr + 1) & 3][i]     + win[(rr + 1) & 3][i + 2]) - c2;
            const float lap1 = (win[ rr      & 3][i + 1] + win[(rr + 2) & 3][i + 1]) - c2;
            const float lap2 = (win[ rr      & 3][i + 2] + win[(rr + 2) & 3][i])     - c2;
            const float lap3 = (win[ rr      & 3][i]     + win[(rr + 2) & 3][i + 2]) - c2;
            o[i] = fmaxf(fmaxf(lap0, lap1), fmaxf(lap2, lap3));
        }

        float* dp = dst + (h0 + rr) * W + w0;
        *(float4*)(dp)     = make_float4(o[0], o[1], o[2], o[3]);
        *(float4*)(dp + 4) = make_float4(o[4], o[5], o[6], o[7]);
    }
}

extern "C" void kernel_launch(void* const* d_in, const int* in_sizes, int n_in,
                              void* d_out, int out_size) {
    const float* x = (const float*)d_in[0];
    float* out = (float*)d_out;

    const int n_img = in_sizes[0] / (H * W);  // B*C = 48

    dim3 block(128);                        // 64 wide x 2 row-strips
    dim3 grid(H / (2 * RPT), n_img);        // 32 x 48 = 1536 blocks
    maxlap_kernel<<<grid, block>>>(x, out);
}

// round 4
// speedup vs baseline: 1.2581x; 1.2581x over previous
#include <cuda_runtime.h>

// out[b,c,h,w] = max over 4 directional 3x3 Laplacians (zero-padded).
// Refactor: every lap_k = s_k - 2*c with
//   s0 = x[h,w-1]+x[h,w+1], s1 = x[h-1,w]+x[h+1,w],
//   s2 = x[h-1,w+1]+x[h+1,w-1], s3 = x[h-1,w-1]+x[h+1,w+1]
// so out = max(s0,s1,s2,s3) - 2*c   (one FFMA instead of 4 subtractions).

#define W   512
#define H   512
#define RPT 8    // rows per thread

// Load 6-wide window [w0-1 .. w0+4] of row h, zero-padded.
__device__ __forceinline__ void load_row6(const float* __restrict__ img,
                                          int h, int w0, float a[6]) {
    if ((unsigned)h >= (unsigned)H) {
        #pragma unroll
        for (int i = 0; i < 6; i++) a[i] = 0.f;
        return;
    }
    const float* row = img + h * W;
    float4 v = __ldg((const float4*)(row + w0));
    a[1] = v.x; a[2] = v.y; a[3] = v.z; a[4] = v.w;
    a[0] = (w0 > 0)     ? __ldg(row + w0 - 1) : 0.f;  // L1 hit
    a[5] = (w0 + 4 < W) ? __ldg(row + w0 + 4) : 0.f;  // L1 hit
}

__global__ __launch_bounds__(128, 12)
void maxlap_kernel(const float* __restrict__ x, float* __restrict__ out) {
    const int img = blockIdx.y;
    const int h0  = blockIdx.x * RPT;
    const int w0  = threadIdx.x * 4;   // 128 threads cover the full 512 row

    const float* in  = x   + (size_t)img * H * W;
    float*       dst = out + (size_t)img * H * W;

    // 3 rotating windows, fully unrolled modular indexing (no roll MOVs).
    float win[3][6];
    load_row6(in, h0 - 1, w0, win[0]);
    load_row6(in, h0,     w0, win[1]);

    #pragma unroll
    for (int rr = 0; rr < RPT; rr++) {
        float* t = win[ rr      % 3];
        float* m = win[(rr + 1) % 3];
        float* b = win[(rr + 2) % 3];
        load_row6(in, h0 + rr + 1, w0, b);

        float4 o;
        float* op = (float*)&o;
        #pragma unroll
        for (int i = 0; i < 4; i++) {
            const float s0 = m[i]     + m[i + 2];
            const float s1 = t[i + 1] + b[i + 1];
            const float s2 = t[i + 2] + b[i];
            const float s3 = t[i]     + b[i + 2];
            const float ms = fmaxf(fmaxf(s0, s1), fmaxf(s2, s3));
            op[i] = fmaf(-2.f, m[i + 1], ms);
        }
        *(float4*)(dst + (h0 + rr) * W + w0) = o;
    }
}

extern "C" void kernel_launch(void* const* d_in, const int* in_sizes, int n_in,
                              void* d_out, int out_size) {
    const float* x = (const float*)d_in[0];
    float* out = (float*)d_out;

    const int n_img = in_sizes[0] / (H * W);  // B*C = 48

    dim3 block(W / 4);               // 128 threads = one full row
    dim3 grid(H / RPT, n_img);       // 64 x 48 = 3072 blocks
    maxlap_kernel<<<grid, block>>>(x, out);
}